// round 4
// baseline (speedup 1.0000x reference)
#include <cuda_runtime.h>
#include <cuda_bf16.h>
#include <cstdint>

// FinDiffNonUniform: yd[i,b] = sum_s w[i,s] * y[i + off[i,s], b]
// N=8192, B=4096, S=7, fp32.
//
// R4: R1-R3 all pinned at ~4.95 TB/s DRAM regardless of occupancy or L2
// amplification -> suspect the LDG/L1tex read path. Move y reads onto the
// TMA bulk path (cp.async.bulk -> SMEM, bypasses L1tex), double-buffered
// 22-row chunks per CTA, register-window compute from SMEM.

#define S_W 7
#define TPB_F 128
#define STRIPE 512                         // floats per CTA stripe
#define GROUP_ROWS 64                      // output rows per CTA
#define CH 16                              // output rows per chunk
#define NCHUNK (GROUP_ROWS / CH)           // 4
#define BUF_ROWS (CH + 6)                  // 22
#define ROW_BYTES (STRIPE * 4)             // 2048
#define BUF_BYTES (BUF_ROWS * ROW_BYTES)   // 45056

// smem layout (dynamic)
#define OFF_BUFS   0
#define OFF_COEF   (2 * BUF_BYTES)                         // 90112
#define OFF_OFFS   (OFF_COEF + GROUP_ROWS * S_W * 4)       // 91904
#define OFF_MBAR   (OFF_OFFS + GROUP_ROWS * S_W * 4)       // 93696
#define OFF_FLAG   (OFF_MBAR + 16)                         // 93712
#define SMEM_TOTAL (OFF_FLAG + 16)                         // 93728

__device__ __forceinline__ uint32_t smem_u32(const void* p) {
    uint32_t a;
    asm("{ .reg .u64 t; cvta.to.shared.u64 t, %1; cvt.u32.u64 %0, t; }"
        : "=r"(a) : "l"(p));
    return a;
}

__device__ __forceinline__ void mbar_wait(uint32_t mb, uint32_t parity) {
    asm volatile(
        "{\n\t"
        ".reg .pred P;\n\t"
        "WL%=:\n\t"
        "mbarrier.try_wait.parity.acquire.cta.shared::cta.b64 P, [%0], %1, 0x989680;\n\t"
        "@P bra WD%=;\n\t"
        "bra WL%=;\n\t"
        "WD%=:\n\t"
        "}" :: "r"(mb), "r"(parity) : "memory");
}

__global__ __launch_bounds__(TPB_F)
void findiff_tma_kernel(const float* __restrict__ y,
                        const float* __restrict__ coef,
                        const int* __restrict__ offs,
                        float* __restrict__ out,
                        int N, int B)
{
    extern __shared__ char smem[];
    float* bufs  = (float*)(smem + OFF_BUFS);
    float* s_w   = (float*)(smem + OFF_COEF);
    int*   s_o   = (int*)  (smem + OFF_OFFS);
    int*   s_flag = (int*) (smem + OFF_FLAG);
    const uint32_t mbar0 = smem_u32(smem + OFF_MBAR);

    const int t      = threadIdx.x;
    const int stripe = blockIdx.x;
    const int r0     = blockIdx.y * GROUP_ROWS;
    const int col    = stripe * STRIPE + t * 4;

    if (t == 0) {
        *s_flag = 1;
        asm volatile("mbarrier.init.shared.b64 [%0], %1;" :: "r"(mbar0),     "r"(1u) : "memory");
        asm volatile("mbarrier.init.shared.b64 [%0], %1;" :: "r"(mbar0 + 8), "r"(1u) : "memory");
    }
    __syncthreads();

    // coefficient / offset slab for this 64-row group; verify centered
    for (int k = t; k < GROUP_ROWS * S_W; k += TPB_F) {
        int gi = r0 * S_W + k;
        s_w[k] = coef[gi];
        int o  = offs[gi];
        s_o[k] = o;
        if (o != (k % S_W) - 3) *s_flag = 0;   // benign race: all write 0
    }
    __syncthreads();

    const bool interior = (r0 >= 3) && (r0 + GROUP_ROWS + 2 <= N - 1) && (*s_flag != 0);

    if (interior) {
        // ---- TMA double-buffered pipeline ----
        const uint32_t dst_base = smem_u32(bufs);

        // issue chunk c into buffer b (elected thread)
        auto issue = [&](int c, int b) {
            if (t == 0) {
                const uint32_t mb = mbar0 + b * 8;
                asm volatile(
                    "mbarrier.arrive.expect_tx.shared::cta.b64 _, [%0], %1;"
                    :: "r"(mb), "r"((uint32_t)BUF_BYTES) : "memory");
                const float* src = y + ((size_t)(r0 + c * CH - 3) * (size_t)B
                                        + (size_t)stripe * STRIPE);
                const uint32_t dst = dst_base + (uint32_t)b * BUF_BYTES;
                #pragma unroll
                for (int j = 0; j < BUF_ROWS; ++j) {
                    asm volatile(
                        "cp.async.bulk.shared::cta.global.mbarrier::complete_tx::bytes "
                        "[%0], [%1], %2, [%3];"
                        :: "r"(dst + j * ROW_BYTES),
                           "l"(src + (size_t)j * (size_t)B),
                           "r"((uint32_t)ROW_BYTES),
                           "r"(mb) : "memory");
                }
            }
        };

        int ph0 = 0, ph1 = 0;
        issue(0, 0);

        #pragma unroll
        for (int c = 0; c < NCHUNK; ++c) {
            const int b = c & 1;
            if (c + 1 < NCHUNK) issue(c + 1, (c + 1) & 1);

            if (b == 0) { mbar_wait(mbar0,     ph0); ph0 ^= 1; }
            else        { mbar_wait(mbar0 + 8, ph1); ph1 ^= 1; }

            const float* bbase = bufs + (size_t)b * (BUF_BYTES / 4) + t * 4;

            #pragma unroll
            for (int p = 0; p < 2; ++p) {
                float4 win[14];
                #pragma unroll
                for (int k = 0; k < 14; ++k)
                    win[k] = *reinterpret_cast<const float4*>(bbase + (8 * p + k) * STRIPE);

                #pragma unroll
                for (int r = 0; r < 8; ++r) {
                    const int row = c * CH + 8 * p + r;     // within group
                    float4 acc = make_float4(0.f, 0.f, 0.f, 0.f);
                    #pragma unroll
                    for (int s = 0; s < S_W; ++s) {
                        const float  w = s_w[row * S_W + s];
                        const float4 v = win[r + s];
                        acc.x = fmaf(w, v.x, acc.x);
                        acc.y = fmaf(w, v.y, acc.y);
                        acc.z = fmaf(w, v.z, acc.z);
                        acc.w = fmaf(w, v.w, acc.w);
                    }
                    *reinterpret_cast<float4*>(
                        out + (size_t)(r0 + row) * (size_t)B + col) = acc;
                }
            }
            __syncthreads();   // all consumers done with buffer b before reuse
        }
    } else {
        // ---- generic path: per-row gather (boundary / non-centered) ----
        for (int r = 0; r < GROUP_ROWS; ++r) {
            const int i = r0 + r;
            if (i >= N) break;
            float4 acc = make_float4(0.f, 0.f, 0.f, 0.f);
            #pragma unroll
            for (int s = 0; s < S_W; ++s) {
                const float w = s_w[r * S_W + s];
                const int   j = i + s_o[r * S_W + s];
                const float4 v = *reinterpret_cast<const float4*>(
                    y + (size_t)j * (size_t)B + col);
                acc.x = fmaf(w, v.x, acc.x);
                acc.y = fmaf(w, v.y, acc.y);
                acc.z = fmaf(w, v.z, acc.z);
                acc.w = fmaf(w, v.w, acc.w);
            }
            *reinterpret_cast<float4*>(out + (size_t)i * (size_t)B + col) = acc;
        }
    }
}

// Fully generic scalar fallback (any N, B).
__global__ void findiff_scalar_kernel(const float* __restrict__ y,
                                      const float* __restrict__ coef,
                                      const int* __restrict__ offs,
                                      float* __restrict__ out,
                                      int N, int B)
{
    const long long total = (long long)N * B;
    for (long long idx = (long long)blockIdx.x * blockDim.x + threadIdx.x;
         idx < total;
         idx += (long long)gridDim.x * blockDim.x) {
        const int i = (int)(idx / B);
        const int b = (int)(idx % B);
        float acc = 0.f;
        #pragma unroll
        for (int s = 0; s < S_W; ++s) {
            const float w = coef[i * S_W + s];
            const int   j = i + offs[i * S_W + s];
            acc = fmaf(w, y[(size_t)j * (size_t)B + b], acc);
        }
        out[idx] = acc;
    }
}

extern "C" void kernel_launch(void* const* d_in, const int* in_sizes, int n_in,
                              void* d_out, int out_size)
{
    const float* y    = (const float*)d_in[0];
    const float* coef = (const float*)d_in[1];
    const int*   offs = (const int*)d_in[2];
    float* out = (float*)d_out;

    const int N = in_sizes[1] / S_W;       // all_coefficients is [N, 7]
    const int B = in_sizes[0] / N;         // y is [N, B]

    if ((B % STRIPE) == 0 && (N % GROUP_ROWS) == 0 && N >= 3 * GROUP_ROWS) {
        cudaFuncSetAttribute(findiff_tma_kernel,
                             cudaFuncAttributeMaxDynamicSharedMemorySize,
                             SMEM_TOTAL);
        dim3 grid(B / STRIPE, N / GROUP_ROWS);
        findiff_tma_kernel<<<grid, TPB_F, SMEM_TOTAL>>>(y, coef, offs, out, N, B);
    } else {
        const long long total = (long long)N * B;
        int blocks = (int)((total + 255) / 256);
        if (blocks > 65535 * 32) blocks = 65535 * 32;
        findiff_scalar_kernel<<<blocks, 256>>>(y, coef, offs, out, N, B);
    }
}

// round 5
// speedup vs baseline: 1.3620x; 1.3620x over previous
#include <cuda_runtime.h>
#include <cuda_bf16.h>

// FinDiffNonUniform: yd[i,b] = sum_s w[i,s] * y[i + off[i,s], b]
// N=8192, B=4096, S=7, fp32.
//
// R5: chip is capped on TOTAL L2-slice traffic (~14 TB/s @NAT, measured
// consistently in R1/R3). Cut SM-side read amplification 1.75x -> 1.19x
// with a TR=32 rolling register window, while keeping the latency hiding
// that R2 lost: float2 lanes (small window regs), prefetch distance 3,
// 2048-CTA grid, <=51 regs (5 CTAs/SM).

#define S_W 7
#define TR 32
#define TPB 256
#define VEC 2
#define PF 3
#define BUF (S_W + PF)            // 10 live rows
#define COLS_PER_BLOCK (TPB * VEC)

__global__ __launch_bounds__(TPB, 5)
void findiff_r5_kernel(const float* __restrict__ y,
                       const float* __restrict__ coef,
                       const int* __restrict__ offs,
                       float* __restrict__ out,
                       int N, int B)
{
    __shared__ float s_w[TR * S_W];
    __shared__ int   s_o[TR * S_W];
    __shared__ int   s_centered;

    const int t  = threadIdx.x;
    const int i0 = blockIdx.y * TR;

    if (t == 0) s_centered = 1;
    __syncthreads();

    // cooperative load of this tile's 32x7 coefficient / offset slab
    for (int k = t; k < TR * S_W; k += TPB) {
        int gidx = i0 * S_W + k;
        if (gidx < N * S_W) {
            s_w[k] = coef[gidx];
            int o  = offs[gidx];
            s_o[k] = o;
            if (o != (k % S_W) - 3) s_centered = 0;
        } else {
            s_w[k] = 0.0f;
            s_o[k] = 0;
        }
    }
    __syncthreads();

    const int col = blockIdx.x * COLS_PER_BLOCK + t * VEC;
    if (col >= B) return;

    const bool interior = (i0 >= 3) && (i0 + TR + 2 <= N - 1) && s_centered;

    if (interior) {
        // ---- fast path: rolling window, static offsets s-3, PF=3 ----
        const float* base  = y   + (size_t)(i0 - 3) * (size_t)B + col;
        float*       obase = out + (size_t)i0       * (size_t)B + col;

        float2 buf[BUF];
        #pragma unroll
        for (int k = 0; k < BUF; ++k)
            buf[k] = *reinterpret_cast<const float2*>(base + (size_t)k * (size_t)B);

        #pragma unroll
        for (int r = 0; r < TR; ++r) {
            // prefetch row (BUF + r) of the TR+6-row span (compile-time guard)
            float2 nxt = buf[BUF - 1];
            if (BUF + r <= TR + 5)
                nxt = *reinterpret_cast<const float2*>(
                          base + (size_t)(BUF + r) * (size_t)B);

            float2 acc = make_float2(0.f, 0.f);
            #pragma unroll
            for (int s = 0; s < S_W; ++s) {
                const float  w = s_w[r * S_W + s];
                const float2 v = buf[s];
                acc.x = fmaf(w, v.x, acc.x);
                acc.y = fmaf(w, v.y, acc.y);
            }
            *reinterpret_cast<float2*>(obase + (size_t)r * (size_t)B) = acc;

            // shift window (register renaming under full unroll)
            #pragma unroll
            for (int k = 0; k < BUF - 1; ++k) buf[k] = buf[k + 1];
            buf[BUF - 1] = nxt;
        }
    } else {
        // ---- generic path: per-row gather (boundary tiles only) ----
        #pragma unroll 4
        for (int r = 0; r < TR; ++r) {
            const int i = i0 + r;
            if (i >= N) break;
            float2 acc = make_float2(0.f, 0.f);
            #pragma unroll
            for (int s = 0; s < S_W; ++s) {
                const float w = s_w[r * S_W + s];
                const int   j = i + s_o[r * S_W + s];
                const float2 v = *reinterpret_cast<const float2*>(
                    y + (size_t)j * (size_t)B + col);
                acc.x = fmaf(w, v.x, acc.x);
                acc.y = fmaf(w, v.y, acc.y);
            }
            *reinterpret_cast<float2*>(out + (size_t)i * (size_t)B + col) = acc;
        }
    }
}

// Fully generic scalar fallback (any N, B).
__global__ void findiff_scalar_kernel(const float* __restrict__ y,
                                      const float* __restrict__ coef,
                                      const int* __restrict__ offs,
                                      float* __restrict__ out,
                                      int N, int B)
{
    const long long total = (long long)N * B;
    for (long long idx = (long long)blockIdx.x * blockDim.x + threadIdx.x;
         idx < total;
         idx += (long long)gridDim.x * blockDim.x) {
        const int i = (int)(idx / B);
        const int b = (int)(idx % B);
        float acc = 0.f;
        #pragma unroll
        for (int s = 0; s < S_W; ++s) {
            const float w = coef[i * S_W + s];
            const int   j = i + offs[i * S_W + s];
            acc = fmaf(w, y[(size_t)j * (size_t)B + b], acc);
        }
        out[idx] = acc;
    }
}

extern "C" void kernel_launch(void* const* d_in, const int* in_sizes, int n_in,
                              void* d_out, int out_size)
{
    const float* y    = (const float*)d_in[0];
    const float* coef = (const float*)d_in[1];
    const int*   offs = (const int*)d_in[2];
    float* out = (float*)d_out;

    const int N = in_sizes[1] / S_W;       // all_coefficients is [N, 7]
    const int B = in_sizes[0] / N;         // y is [N, B]

    if ((B % COLS_PER_BLOCK) == 0) {
        dim3 grid(B / COLS_PER_BLOCK, (N + TR - 1) / TR);
        findiff_r5_kernel<<<grid, TPB>>>(y, coef, offs, out, N, B);
    } else {
        const long long total = (long long)N * B;
        int blocks = (int)((total + 255) / 256);
        if (blocks > 65535 * 32) blocks = 65535 * 32;
        findiff_scalar_kernel<<<blocks, 256>>>(y, coef, offs, out, N, B);
    }
}

// round 6
// speedup vs baseline: 1.6484x; 1.2103x over previous
#include <cuda_runtime.h>
#include <cuda_bf16.h>

// FinDiffNonUniform: yd[i,b] = sum_s w[i,s] * y[i + off[i,s], b]
// N=8192, B=4096, S=7, fp32.
//
// R6: best regime = front-batched 14-row register window (max MLP) + high
// occupancy (R3, 45.3us). Remove issue-slot overhead that limits latency
// hiding: (1) coefficients loaded as 2x LDS.128 per row from padded smem
// (16 wide LDS vs 56 scalar LDS per thread-tile), (2) __stcs streaming
// stores so the write stream doesn't evict y halo lines from L2.

#define S_W 7
#define SP  8                      // padded stencil stride
#define TR 8
#define TPB 256
#define VEC 2
#define WIN (TR + 6)               // 14-row window
#define COLS_PER_BLOCK (TPB * VEC)

__global__ __launch_bounds__(TPB, 6)
void findiff_r6_kernel(const float* __restrict__ y,
                       const float* __restrict__ coef,
                       const int* __restrict__ offs,
                       float* __restrict__ out,
                       int N, int B)
{
    __shared__ __align__(16) float s_w[TR * SP];   // padded: [TR][8]
    __shared__ int   s_o[TR * S_W];
    __shared__ int   s_centered;

    const int t  = threadIdx.x;
    const int i0 = blockIdx.y * TR;

    if (t == 0) s_centered = 1;
    if (t < TR) s_w[t * SP + S_W] = 0.0f;          // zero the pad lane
    __syncthreads();

    if (t < TR * S_W) {
        const int r = t / S_W, s = t % S_W;
        int gidx = i0 * S_W + t;
        if (gidx < N * S_W) {
            s_w[r * SP + s] = coef[gidx];
            int o = offs[gidx];
            s_o[t] = o;
            if (o != s - 3) s_centered = 0;
        } else {
            s_w[r * SP + s] = 0.0f;
            s_o[t] = 0;
        }
    }
    __syncthreads();

    const int col = blockIdx.x * COLS_PER_BLOCK + t * VEC;
    if (col >= B) return;

    const bool interior = (i0 >= 3) && (i0 + TR + 2 <= N - 1) && s_centered;

    if (interior) {
        // ---- fast path: front-batched register window, offsets = s-3 ----
        float2 win[WIN];
        const float* base = y + (size_t)(i0 - 3) * (size_t)B + col;
        #pragma unroll
        for (int k = 0; k < WIN; ++k)
            win[k] = *reinterpret_cast<const float2*>(base + (size_t)k * (size_t)B);

        float* obase = out + (size_t)i0 * (size_t)B + col;
        #pragma unroll
        for (int r = 0; r < TR; ++r) {
            // wide coefficient loads (broadcast, conflict-free)
            const float4 c0 = *reinterpret_cast<const float4*>(&s_w[r * SP]);
            const float4 c1 = *reinterpret_cast<const float4*>(&s_w[r * SP + 4]);
            const float w[S_W] = {c0.x, c0.y, c0.z, c0.w, c1.x, c1.y, c1.z};

            float2 acc = make_float2(0.f, 0.f);
            #pragma unroll
            for (int s = 0; s < S_W; ++s) {
                const float2 v = win[r + s];
                acc.x = fmaf(w[s], v.x, acc.x);
                acc.y = fmaf(w[s], v.y, acc.y);
            }
            __stcs(reinterpret_cast<float2*>(obase + (size_t)r * (size_t)B), acc);
        }
    } else {
        // ---- generic path: per-row gather (boundary tiles only) ----
        #pragma unroll
        for (int r = 0; r < TR; ++r) {
            const int i = i0 + r;
            if (i >= N) break;
            float2 acc = make_float2(0.f, 0.f);
            #pragma unroll
            for (int s = 0; s < S_W; ++s) {
                const float wv = s_w[r * SP + s];
                const int   j  = i + s_o[r * S_W + s];
                const float2 v = *reinterpret_cast<const float2*>(
                    y + (size_t)j * (size_t)B + col);
                acc.x = fmaf(wv, v.x, acc.x);
                acc.y = fmaf(wv, v.y, acc.y);
            }
            *reinterpret_cast<float2*>(out + (size_t)i * (size_t)B + col) = acc;
        }
    }
}

// Fully generic scalar fallback (any N, B).
__global__ void findiff_scalar_kernel(const float* __restrict__ y,
                                      const float* __restrict__ coef,
                                      const int* __restrict__ offs,
                                      float* __restrict__ out,
                                      int N, int B)
{
    const long long total = (long long)N * B;
    for (long long idx = (long long)blockIdx.x * blockDim.x + threadIdx.x;
         idx < total;
         idx += (long long)gridDim.x * blockDim.x) {
        const int i = (int)(idx / B);
        const int b = (int)(idx % B);
        float acc = 0.f;
        #pragma unroll
        for (int s = 0; s < S_W; ++s) {
            const float w = coef[i * S_W + s];
            const int   j = i + offs[i * S_W + s];
            acc = fmaf(w, y[(size_t)j * (size_t)B + b], acc);
        }
        out[idx] = acc;
    }
}

extern "C" void kernel_launch(void* const* d_in, const int* in_sizes, int n_in,
                              void* d_out, int out_size)
{
    const float* y    = (const float*)d_in[0];
    const float* coef = (const float*)d_in[1];
    const int*   offs = (const int*)d_in[2];
    float* out = (float*)d_out;

    const int N = in_sizes[1] / S_W;       // all_coefficients is [N, 7]
    const int B = in_sizes[0] / N;         // y is [N, B]

    if ((B % COLS_PER_BLOCK) == 0) {
        dim3 grid(B / COLS_PER_BLOCK, (N + TR - 1) / TR);
        findiff_r6_kernel<<<grid, TPB>>>(y, coef, offs, out, N, B);
    } else {
        const long long total = (long long)N * B;
        int blocks = (int)((total + 255) / 256);
        if (blocks > 65535 * 32) blocks = 65535 * 32;
        findiff_scalar_kernel<<<blocks, 256>>>(y, coef, offs, out, N, B);
    }
}